// round 12
// baseline (speedup 1.0000x reference)
#include <cuda_runtime.h>
#include <cuda_bf16.h>
#include <math.h>

// Problem constants
#define Bc 4
#define Nc 2048
#define Dc 256
#define Hc 4
#define DHc 64
#define Mc (Bc * Nc)          // 8192 rows
#define EPSc 1e-8f
#define LDH 72                // smem row pitch in halves (144B: ldsm conflict-free)
#define QSCALE 0.1803368801111204f   // 0.125 * log2(e)
#define ONESBF 0x3F803F80u    // bf16x2 (1.0, 1.0)
#define NSPLIT 2
#define ROWS_BH (Bc * Hc * Nc)       // 32768 attention rows

// Scratch (device globals; no allocation allowed)
__device__ __nv_bfloat16 buf_hb[Mc * Dc];          // normalized h, bf16
__device__ __nv_bfloat16 buf_q[ROWS_BH * DHc];     // pre-scaled by QSCALE
__device__ __nv_bfloat16 buf_k[ROWS_BH * DHc];
__device__ __nv_bfloat16 buf_v[ROWS_BH * DHc];
__device__ __nv_bfloat16 buf_yb[Mc * Dc];          // attention out, bf16
__device__ float buf_po[NSPLIT * ROWS_BH * DHc];   // partial O (unnormalized)
__device__ float buf_l[NSPLIT][ROWS_BH];           // partial row sums
__device__ __nv_bfloat16 wqkv_b[Dc * 3 * Dc];      // bf16 weights
__device__ __nv_bfloat16 wout_b[Dc * Dc];
__device__ __nv_bfloat16 wgate_b[Dc * Dc];

// ---------------------------------------------------------------------------
// helpers
// ---------------------------------------------------------------------------
__device__ __forceinline__ unsigned pack_bf(float x, float y) {
    __nv_bfloat162 h = __float22bfloat162_rn(make_float2(x, y));
    return *reinterpret_cast<unsigned*>(&h);
}
// packed bf16x2 2^x of a float pair: result = (ex2(lo), ex2(hi)) as bf16x2
__device__ __forceinline__ unsigned ex2b(float lo, float hi) {
    unsigned p, r;
    asm("cvt.rn.bf16x2.f32 %0, %1, %2;" : "=r"(p) : "f"(hi), "f"(lo));
    asm("ex2.approx.ftz.bf16x2 %0, %1;" : "=r"(r) : "r"(p));
    return r;
}
__device__ __forceinline__ void mma16(float4& d, unsigned a0, unsigned a1,
                                      unsigned a2, unsigned a3,
                                      unsigned b0, unsigned b1) {
    asm volatile(
        "mma.sync.aligned.m16n8k16.row.col.f32.bf16.bf16.f32 "
        "{%0,%1,%2,%3},{%4,%5,%6,%7},{%8,%9},{%0,%1,%2,%3};"
        : "+f"(d.x), "+f"(d.y), "+f"(d.z), "+f"(d.w)
        : "r"(a0), "r"(a1), "r"(a2), "r"(a3), "r"(b0), "r"(b1));
}
__device__ __forceinline__ void ldsm4(unsigned& r0, unsigned& r1, unsigned& r2,
                                      unsigned& r3, const void* p) {
    unsigned a = (unsigned)__cvta_generic_to_shared(p);
    asm volatile("ldmatrix.sync.aligned.m8n8.x4.shared.b16 {%0,%1,%2,%3},[%4];"
                 : "=r"(r0), "=r"(r1), "=r"(r2), "=r"(r3) : "r"(a));
}
__device__ __forceinline__ void ldsm4t(unsigned& r0, unsigned& r1, unsigned& r2,
                                       unsigned& r3, const void* p) {
    unsigned a = (unsigned)__cvta_generic_to_shared(p);
    asm volatile("ldmatrix.sync.aligned.m8n8.x4.trans.shared.b16 {%0,%1,%2,%3},[%4];"
                 : "=r"(r0), "=r"(r1), "=r"(r2), "=r"(r3) : "r"(a));
}
__device__ __forceinline__ void cpasync16(void* dst, const void* src) {
    unsigned d = (unsigned)__cvta_generic_to_shared(dst);
    asm volatile("cp.async.ca.shared.global [%0], [%1], 16;" :: "r"(d), "l"(src));
}
__device__ __forceinline__ void cp_commit() {
    asm volatile("cp.async.commit_group;" ::: "memory");
}
__device__ __forceinline__ void cp_wait_all() {
    asm volatile("cp.async.wait_group 0;" ::: "memory");
}

// ---------------------------------------------------------------------------
// 0) convert all weights to bf16 (once per launch; tiny)
// ---------------------------------------------------------------------------
__global__ void convw_kernel(const float* __restrict__ wq,
                             const float* __restrict__ wo,
                             const float* __restrict__ wg) {
    int i = blockIdx.x * blockDim.x + threadIdx.x;  // float4 index < 81920
    const float* src;
    __nv_bfloat16* dst;
    int off;
    if (i < 49152)      { src = wq; dst = wqkv_b;  off = i; }
    else if (i < 65536) { src = wo; dst = wout_b;  off = i - 49152; }
    else                { src = wg; dst = wgate_b; off = i - 65536; }
    float4 v = reinterpret_cast<const float4*>(src)[off];
    *reinterpret_cast<uint2*>(dst + off * 4) =
        make_uint2(pack_bf(v.x, v.y), pack_bf(v.z, v.w));
}

// ---------------------------------------------------------------------------
// 1) zero-centered RMSNorm -> bf16 h
// ---------------------------------------------------------------------------
__global__ void rmsnorm_kernel(const float* __restrict__ x,
                               const float* __restrict__ g) {
    int row = blockIdx.x;
    int t = threadIdx.x;
    float v = x[row * Dc + t];
    __shared__ float red[8];
    float s = v;
    #pragma unroll
    for (int o = 16; o; o >>= 1) s += __shfl_xor_sync(0xffffffffu, s, o);
    if ((t & 31) == 0) red[t >> 5] = s;
    __syncthreads();
    float tot = 0.f;
    #pragma unroll
    for (int i = 0; i < 8; i++) tot += red[i];
    float mean = tot * (1.f / Dc);
    float x0 = v - mean;
    float s2 = x0 * x0;
    #pragma unroll
    for (int o = 16; o; o >>= 1) s2 += __shfl_xor_sync(0xffffffffu, s2, o);
    __syncthreads();
    if ((t & 31) == 0) red[t >> 5] = s2;
    __syncthreads();
    float tot2 = 0.f;
    #pragma unroll
    for (int i = 0; i < 8; i++) tot2 += red[i];
    float rinv = rsqrtf(tot2 * (1.f / Dc) + EPSc);
    buf_hb[row * Dc + t] = __float2bfloat16(x0 * rinv * g[t]);
}

// ---------------------------------------------------------------------------
// 2) pipelined bf16 mma GEMM mainloop (cp.async 2-stage, single barrier/iter)
// ---------------------------------------------------------------------------
template <int NOUT>
__device__ __forceinline__ void gemm_main(
    const __nv_bfloat16* __restrict__ A, const __nv_bfloat16* __restrict__ W,
    __nv_bfloat16 (&As)[2][64][LDH], __nv_bfloat16 (&Ws)[2][64][LDH],
    float4 acc[8], int rowBase, int colBase) {
    int tid = threadIdx.x;
    int wid = tid >> 5, lane = tid & 31;
    int wr = wid * 16;
    #pragma unroll
    for (int i = 0; i < 8; i++) acc[i] = make_float4(0.f, 0.f, 0.f, 0.f);

    int lr = tid >> 3, lc8 = (tid & 7) * 8;

    auto load_tile = [&](int s, int k0) {
        #pragma unroll
        for (int j = 0; j < 4; j++) {
            int r = lr + 16 * j;
            cpasync16(&As[s][r][lc8], &A[(rowBase + r) * Dc + k0 + lc8]);
            cpasync16(&Ws[s][r][lc8], &W[(k0 + r) * NOUT + colBase + lc8]);
        }
    };

    load_tile(0, 0);
    cp_commit();

    #pragma unroll
    for (int kc = 0; kc < 4; kc++) {
        cp_wait_all();
        __syncthreads();
        if (kc < 3) {
            load_tile((kc + 1) & 1, (kc + 1) * 64);
            cp_commit();
        }
        int s = kc & 1;
        #pragma unroll
        for (int ks = 0; ks < 4; ks++) {
            unsigned a0, a1, a2, a3;
            ldsm4(a0, a1, a2, a3, &As[s][wr + (lane & 15)][ks * 16 + (lane >> 4) * 8]);
            #pragma unroll
            for (int p = 0; p < 4; p++) {
                unsigned b0, b1, b2, b3;
                ldsm4t(b0, b1, b2, b3,
                       &Ws[s][ks * 16 + (lane & 7) + 8 * ((lane >> 3) & 1)]
                            [p * 16 + (lane >> 4) * 8]);
                mma16(acc[2 * p], a0, a1, a2, a3, b0, b1);
                mma16(acc[2 * p + 1], a0, a1, a2, a3, b2, b3);
            }
        }
    }
}

// QKV GEMM with fused bias + RoPE + head scatter (bf16 outputs; q pre-scaled)
__global__ __launch_bounds__(128) void gemm_qkv_kernel(
    const float* __restrict__ bias, const float* __restrict__ freqs) {
    __shared__ __align__(16) __nv_bfloat16 As[2][64][LDH];
    __shared__ __align__(16) __nv_bfloat16 Ws[2][64][LDH];
    int rowBase = blockIdx.y * 64;
    int colBase = blockIdx.x * 64;
    float4 acc[8];
    gemm_main<3 * Dc>(buf_hb, wqkv_b, As, Ws, acc, rowBase, colBase);

    int tid = threadIdx.x;
    int wid = tid >> 5, lane = tid & 31;
    int gid = lane >> 2, tig = lane & 3;
    int sec = colBase >> 8;  // 0=q 1=k 2=v (uniform per block)
    unsigned* dst = sec == 0 ? reinterpret_cast<unsigned*>(buf_q)
                  : sec == 1 ? reinterpret_cast<unsigned*>(buf_k)
                             : reinterpret_cast<unsigned*>(buf_v);
    float scl = sec == 0 ? QSCALE : 1.f;
    int r0 = rowBase + wid * 16 + gid, r1 = r0 + 8;
    int n0 = r0 & (Nc - 1), n1 = r1 & (Nc - 1);
    int b0i = r0 >> 11, b1i = r1 >> 11;
    #pragma unroll
    for (int nt = 0; nt < 8; nt++) {
        int col = colBase + nt * 8 + tig * 2;
        int c = col & 255, h = c >> 6, i = (c & 63) >> 1;
        float bx = bias[col], by = bias[col + 1];
        float v0 = acc[nt].x + bx, v1 = acc[nt].y + by;
        float w0 = acc[nt].z + bx, w1 = acc[nt].w + by;
        if (sec < 2) {
            float2 cs0 = *reinterpret_cast<const float2*>(&freqs[n0 * 64 + i * 2]);
            float2 cs1 = *reinterpret_cast<const float2*>(&freqs[n1 * 64 + i * 2]);
            float t0 = v0 * cs0.x - v1 * cs0.y;
            v1 = v0 * cs0.y + v1 * cs0.x; v0 = t0;
            float t1 = w0 * cs1.x - w1 * cs1.y;
            w1 = w0 * cs1.y + w1 * cs1.x; w0 = t1;
        }
        v0 *= scl; v1 *= scl; w0 *= scl; w1 *= scl;
        dst[((b0i * Hc + h) * Nc + n0) * 32 + i] = pack_bf(v0, v1);
        dst[((b1i * Hc + h) * Nc + n1) * 32 + i] = pack_bf(w0, w1);
    }
}

// Fused out-proj + gate + residual/gating epilogue
__global__ __launch_bounds__(128) void og_final_kernel(
    const float* __restrict__ bo, const float* __restrict__ bg,
    const float* __restrict__ x, float* __restrict__ out) {
    __shared__ __align__(16) __nv_bfloat16 As[2][64][LDH];
    __shared__ __align__(16) __nv_bfloat16 Ws[2][64][LDH];
    int rowBase = blockIdx.y * 64;
    int colBase = blockIdx.x * 64;
    float4 ao[8], ag[8];
    gemm_main<Dc>(buf_yb, wout_b, As, Ws, ao, rowBase, colBase);
    __syncthreads();   // stage reuse boundary between the two GEMMs
    gemm_main<Dc>(buf_hb, wgate_b, As, Ws, ag, rowBase, colBase);

    int tid = threadIdx.x;
    int wid = tid >> 5, lane = tid & 31;
    int gid = lane >> 2, tig = lane & 3;
    int r0 = rowBase + wid * 16 + gid, r1 = r0 + 8;
    #pragma unroll
    for (int nt = 0; nt < 8; nt++) {
        int col = colBase + nt * 8 + tig * 2;
        float box = bo[col], boy = bo[col + 1];
        float bgx = bg[col], bgy = bg[col + 1];
        float g00 = 1.f / (1.f + __expf(-(ag[nt].x + bgx)));
        float g01 = 1.f / (1.f + __expf(-(ag[nt].y + bgy)));
        float g10 = 1.f / (1.f + __expf(-(ag[nt].z + bgx)));
        float g11 = 1.f / (1.f + __expf(-(ag[nt].w + bgy)));
        float2 x0 = *reinterpret_cast<const float2*>(&x[r0 * Dc + col]);
        float2 x1 = *reinterpret_cast<const float2*>(&x[r1 * Dc + col]);
        *reinterpret_cast<float2*>(&out[r0 * Dc + col]) =
            make_float2(x0.x + g00 * (ao[nt].x + box),
                        x0.y + g01 * (ao[nt].y + boy));
        *reinterpret_cast<float2*>(&out[r1 * Dc + col]) =
            make_float2(x1.x + g10 * (ao[nt].z + box),
                        x1.y + g11 * (ao[nt].w + boy));
    }
}

// ---------------------------------------------------------------------------
// 3) Flash attention, KV-split=2 on the lean (168-reg) kernel. Grid 512 ->
//    3+ blocks/SM actually resident now. Each block: 16 K-tiles, writes
//    unnormalized partial O (fp32) + row-sum l. Fixed-max softmax makes
//    partials directly summable (no max bookkeeping in the merge).
// ---------------------------------------------------------------------------
__global__ __launch_bounds__(128, 3) void attn_kernel() {
    __shared__ __align__(16) __nv_bfloat16 Ks[2][64][LDH];
    __shared__ __align__(16) __nv_bfloat16 Vs[2][64][LDH];

    int tid = threadIdx.x;
    int wid = tid >> 5, lane = tid & 31;
    int gid = lane >> 2, tig = lane & 3;
    int bh = blockIdx.x >> 4;     // 16 bh
    int qt = blockIdx.x & 15;     // 16 q tiles of 128
    int split = blockIdx.y;
    int qBase = qt * 128;
    int kb0 = split * (Nc / NSPLIT);
    const __nv_bfloat16* Q = buf_q + bh * Nc * DHc;
    const __nv_bfloat16* K = buf_k + bh * Nc * DHc;
    const __nv_bfloat16* V = buf_v + bh * Nc * DHc;
    int wr = wid * 16;

    int lr = tid >> 3, lc8 = (tid & 7) * 8;
    auto load_kv = [&](int s, int kb) {
        #pragma unroll
        for (int j = 0; j < 4; j++) {
            int r = lr + 16 * j;
            cpasync16(&Ks[s][r][lc8], &K[(kb + r) * DHc + lc8]);
            cpasync16(&Vs[s][r][lc8], &V[(kb + r) * DHc + lc8]);
        }
    };

    load_kv(0, kb0);
    cp_commit();

    // Q A-fragments for both 16-row groups (already scaled by QSCALE)
    unsigned qa[2][4][4];
    #pragma unroll
    for (int g = 0; g < 2; g++) {
        const __nv_bfloat16* qp = Q + (qBase + g * 64 + wr) * DHc;
        #pragma unroll
        for (int ks = 0; ks < 4; ks++) {
            int c = ks * 16 + tig * 2;
            qa[g][ks][0] = *reinterpret_cast<const unsigned*>(&qp[gid * DHc + c]);
            qa[g][ks][1] = *reinterpret_cast<const unsigned*>(&qp[(gid + 8) * DHc + c]);
            qa[g][ks][2] = *reinterpret_cast<const unsigned*>(&qp[gid * DHc + c + 8]);
            qa[g][ks][3] = *reinterpret_cast<const unsigned*>(&qp[(gid + 8) * DHc + c + 8]);
        }
    }

    float4 oacc[2][8];
    float4 lacc[2];   // row sums via ones-mma: .x = row gid, .z = row gid+8
    #pragma unroll
    for (int g = 0; g < 2; g++) {
        lacc[g] = make_float4(0.f, 0.f, 0.f, 0.f);
        #pragma unroll
        for (int i = 0; i < 8; i++) oacc[g][i] = make_float4(0.f, 0.f, 0.f, 0.f);
    }

    #pragma unroll 1
    for (int t = 0; t < Nc / NSPLIT / 64; t++) {
        cp_wait_all();
        __syncthreads();
        if (t < Nc / NSPLIT / 64 - 1) {
            load_kv((t + 1) & 1, kb0 + (t + 1) * 64);
            cp_commit();
        }
        int s = t & 1;

        // Per n-tile p: QK mmas for both groups, then immediate ex2b -> pa.
        unsigned pa[2][4][4];
        #pragma unroll
        for (int p = 0; p < 4; p++) {
            float4 s0[2], s1[2];
            #pragma unroll
            for (int g = 0; g < 2; g++) {
                s0[g] = make_float4(0.f, 0.f, 0.f, 0.f);
                s1[g] = make_float4(0.f, 0.f, 0.f, 0.f);
            }
            #pragma unroll
            for (int ks = 0; ks < 4; ks++) {
                unsigned b0, b1, b2, b3;
                ldsm4(b0, b1, b2, b3,
                      &Ks[s][p * 16 + (lane & 7) + 8 * (lane >> 4)]
                           [ks * 16 + 8 * ((lane >> 3) & 1)]);
                #pragma unroll
                for (int g = 0; g < 2; g++) {
                    mma16(s0[g], qa[g][ks][0], qa[g][ks][1],
                          qa[g][ks][2], qa[g][ks][3], b0, b1);
                    mma16(s1[g], qa[g][ks][0], qa[g][ks][1],
                          qa[g][ks][2], qa[g][ks][3], b2, b3);
                }
            }
            #pragma unroll
            for (int g = 0; g < 2; g++) {
                pa[g][p][0] = ex2b(s0[g].x, s0[g].y);
                pa[g][p][1] = ex2b(s0[g].z, s0[g].w);
                pa[g][p][2] = ex2b(s1[g].x, s1[g].y);
                pa[g][p][3] = ex2b(s1[g].z, s1[g].w);
                mma16(lacc[g], pa[g][p][0], pa[g][p][1],
                      pa[g][p][2], pa[g][p][3], ONESBF, ONESBF);
            }
        }

        // O += P V for both groups (V b-frags loaded once)
        #pragma unroll
        for (int p = 0; p < 4; p++) {
            #pragma unroll
            for (int ks = 0; ks < 4; ks++) {
                unsigned b0, b1, b2, b3;
                ldsm4t(b0, b1, b2, b3,
                       &Vs[s][ks * 16 + (lane & 7) + 8 * ((lane >> 3) & 1)]
                            [p * 16 + (lane >> 4) * 8]);
                #pragma unroll
                for (int g = 0; g < 2; g++) {
                    mma16(oacc[g][2 * p], pa[g][ks][0], pa[g][ks][1],
                          pa[g][ks][2], pa[g][ks][3], b0, b1);
                    mma16(oacc[g][2 * p + 1], pa[g][ks][0], pa[g][ks][1],
                          pa[g][ks][2], pa[g][ks][3], b2, b3);
                }
            }
        }
    }

    // write unnormalized partial O + row sums
    float* po = buf_po + split * (ROWS_BH * DHc);
    #pragma unroll
    for (int g = 0; g < 2; g++) {
        int r0 = bh * Nc + qBase + g * 64 + wr + gid, r1 = r0 + 8;
        #pragma unroll
        for (int nt = 0; nt < 8; nt++) {
            int col = nt * 8 + tig * 2;
            *reinterpret_cast<float2*>(&po[r0 * DHc + col]) =
                make_float2(oacc[g][nt].x, oacc[g][nt].y);
            *reinterpret_cast<float2*>(&po[r1 * DHc + col]) =
                make_float2(oacc[g][nt].z, oacc[g][nt].w);
        }
        if (tig == 0) {
            buf_l[split][r0] = lacc[g].x;
            buf_l[split][r1] = lacc[g].z;
        }
    }
}

// ---------------------------------------------------------------------------
// 4) merge the two KV-split partials -> bf16 buf_yb [b][n][h*64+d]
//    (fixed-max softmax: partials are directly summable)
// ---------------------------------------------------------------------------
__global__ void merge_kernel() {
    int idx = blockIdx.x * blockDim.x + threadIdx.x;   // < ROWS_BH*16
    int row = idx >> 4;          // bh*Nc + n
    int d4 = idx & 15;
    float inv = 1.f / (buf_l[0][row] + buf_l[1][row]);
    float4 a = *reinterpret_cast<const float4*>(&buf_po[row * DHc + d4 * 4]);
    float4 c = *reinterpret_cast<const float4*>(
        &buf_po[ROWS_BH * DHc + row * DHc + d4 * 4]);
    float o0 = (a.x + c.x) * inv;
    float o1 = (a.y + c.y) * inv;
    float o2 = (a.z + c.z) * inv;
    float o3 = (a.w + c.w) * inv;
    int bh = row >> 11, n = row & (Nc - 1);
    int b = bh >> 2, h = bh & 3;
    unsigned* Y = reinterpret_cast<unsigned*>(buf_yb);
    int base = (b * Nc + n) * 128 + h * 32 + d4 * 2;
    Y[base] = pack_bf(o0, o1);
    Y[base + 1] = pack_bf(o2, o3);
}

// ---------------------------------------------------------------------------
extern "C" void kernel_launch(void* const* d_in, const int* in_sizes, int n_in,
                              void* d_out, int out_size) {
    (void)in_sizes; (void)n_in; (void)out_size;
    const float* x      = (const float*)d_in[0];
    const float* freqs  = (const float*)d_in[1];
    const float* g      = (const float*)d_in[2];
    const float* w_qkv  = (const float*)d_in[3];
    const float* b_qkv  = (const float*)d_in[4];
    const float* w_out  = (const float*)d_in[5];
    const float* b_out  = (const float*)d_in[6];
    const float* w_gate = (const float*)d_in[7];
    const float* b_gate = (const float*)d_in[8];
    float* out = (float*)d_out;

    convw_kernel<<<320, 256>>>(w_qkv, w_out, w_gate);
    rmsnorm_kernel<<<Mc, Dc>>>(x, g);
    gemm_qkv_kernel<<<dim3(12, 128), 128>>>(b_qkv, freqs);
    attn_kernel<<<dim3(Bc * Hc * (Nc / 128), NSPLIT), 128>>>();
    merge_kernel<<<(ROWS_BH * 16) / 256, 256>>>();
    og_final_kernel<<<dim3(4, 128), 128>>>(b_out, b_gate, x, out);
}

// round 14
// speedup vs baseline: 1.1159x; 1.1159x over previous
#include <cuda_runtime.h>
#include <cuda_bf16.h>
#include <math.h>

// Problem constants
#define Bc 4
#define Nc 2048
#define Dc 256
#define Hc 4
#define DHc 64
#define Mc (Bc * Nc)          // 8192 rows
#define EPSc 1e-8f
#define LDH 72                // smem row pitch in halves (144B: ldsm conflict-free)
#define QSCALE 0.1803368801111204f   // 0.125 * log2(e)
#define ONESBF 0x3F803F80u    // bf16x2 (1.0, 1.0)

// attention dynamic smem: K[2][128][LDH] + V[2][128][LDH] halves
#define KV_STAGE_B (128 * LDH * 2)          // 18432 bytes per stage
#define ATTN_SMEM  (4 * KV_STAGE_B)         // 73728

// Scratch (device globals; no allocation allowed)
__device__ __nv_bfloat16 buf_hb[Mc * Dc];          // normalized h, bf16
__device__ __nv_bfloat16 buf_q[Bc * Hc * Nc * DHc]; // pre-scaled by QSCALE
__device__ __nv_bfloat16 buf_k[Bc * Hc * Nc * DHc];
__device__ __nv_bfloat16 buf_v[Bc * Hc * Nc * DHc];
__device__ __nv_bfloat16 buf_yb[Mc * Dc];          // attention out, bf16
__device__ __nv_bfloat16 wqkv_b[Dc * 3 * Dc];      // bf16 weights
__device__ __nv_bfloat16 wout_b[Dc * Dc];
__device__ __nv_bfloat16 wgate_b[Dc * Dc];

// ---------------------------------------------------------------------------
// helpers
// ---------------------------------------------------------------------------
__device__ __forceinline__ unsigned pack_bf(float x, float y) {
    __nv_bfloat162 h = __float22bfloat162_rn(make_float2(x, y));
    return *reinterpret_cast<unsigned*>(&h);
}
// packed bf16x2 2^x of a float pair: result = (ex2(lo), ex2(hi)) as bf16x2
__device__ __forceinline__ unsigned ex2b(float lo, float hi) {
    unsigned p, r;
    asm("cvt.rn.bf16x2.f32 %0, %1, %2;" : "=r"(p) : "f"(hi), "f"(lo));
    asm("ex2.approx.ftz.bf16x2 %0, %1;" : "=r"(r) : "r"(p));
    return r;
}
__device__ __forceinline__ void mma16(float4& d, unsigned a0, unsigned a1,
                                      unsigned a2, unsigned a3,
                                      unsigned b0, unsigned b1) {
    asm volatile(
        "mma.sync.aligned.m16n8k16.row.col.f32.bf16.bf16.f32 "
        "{%0,%1,%2,%3},{%4,%5,%6,%7},{%8,%9},{%0,%1,%2,%3};"
        : "+f"(d.x), "+f"(d.y), "+f"(d.z), "+f"(d.w)
        : "r"(a0), "r"(a1), "r"(a2), "r"(a3), "r"(b0), "r"(b1));
}
__device__ __forceinline__ void ldsm4(unsigned& r0, unsigned& r1, unsigned& r2,
                                      unsigned& r3, const void* p) {
    unsigned a = (unsigned)__cvta_generic_to_shared(p);
    asm volatile("ldmatrix.sync.aligned.m8n8.x4.shared.b16 {%0,%1,%2,%3},[%4];"
                 : "=r"(r0), "=r"(r1), "=r"(r2), "=r"(r3) : "r"(a));
}
__device__ __forceinline__ void ldsm4t(unsigned& r0, unsigned& r1, unsigned& r2,
                                       unsigned& r3, const void* p) {
    unsigned a = (unsigned)__cvta_generic_to_shared(p);
    asm volatile("ldmatrix.sync.aligned.m8n8.x4.trans.shared.b16 {%0,%1,%2,%3},[%4];"
                 : "=r"(r0), "=r"(r1), "=r"(r2), "=r"(r3) : "r"(a));
}
__device__ __forceinline__ void cpasync16(void* dst, const void* src) {
    unsigned d = (unsigned)__cvta_generic_to_shared(dst);
    asm volatile("cp.async.ca.shared.global [%0], [%1], 16;" :: "r"(d), "l"(src));
}
__device__ __forceinline__ void cp_commit() {
    asm volatile("cp.async.commit_group;" ::: "memory");
}
__device__ __forceinline__ void cp_wait_all() {
    asm volatile("cp.async.wait_group 0;" ::: "memory");
}

// ---------------------------------------------------------------------------
// 0) fused prologue: zcRMSNorm (blocks 0..1023, warp-per-row) +
//    weight fp32->bf16 conversion (blocks 1024..1343)
// ---------------------------------------------------------------------------
__global__ void pre_kernel(const float* __restrict__ x,
                           const float* __restrict__ g,
                           const float* __restrict__ wq,
                           const float* __restrict__ wo,
                           const float* __restrict__ wg) {
    if (blockIdx.x < 1024) {
        int wid = threadIdx.x >> 5, lane = threadIdx.x & 31;
        int row = blockIdx.x * 8 + wid;
        const float* xr = x + row * Dc + lane * 8;
        float4 a = *reinterpret_cast<const float4*>(xr);
        float4 b = *reinterpret_cast<const float4*>(xr + 4);
        float s = a.x + a.y + a.z + a.w + b.x + b.y + b.z + b.w;
        #pragma unroll
        for (int o = 16; o; o >>= 1) s += __shfl_xor_sync(0xffffffffu, s, o);
        float mean = s * (1.f / Dc);
        float v[8] = {a.x - mean, a.y - mean, a.z - mean, a.w - mean,
                      b.x - mean, b.y - mean, b.z - mean, b.w - mean};
        float s2 = 0.f;
        #pragma unroll
        for (int j = 0; j < 8; j++) s2 += v[j] * v[j];
        #pragma unroll
        for (int o = 16; o; o >>= 1) s2 += __shfl_xor_sync(0xffffffffu, s2, o);
        float rinv = rsqrtf(s2 * (1.f / Dc) + EPSc);
        float4 g0 = *reinterpret_cast<const float4*>(g + lane * 8);
        float4 g1 = *reinterpret_cast<const float4*>(g + lane * 8 + 4);
        uint4 o4;
        o4.x = pack_bf(v[0] * rinv * g0.x, v[1] * rinv * g0.y);
        o4.y = pack_bf(v[2] * rinv * g0.z, v[3] * rinv * g0.w);
        o4.z = pack_bf(v[4] * rinv * g1.x, v[5] * rinv * g1.y);
        o4.w = pack_bf(v[6] * rinv * g1.z, v[7] * rinv * g1.w);
        *reinterpret_cast<uint4*>(buf_hb + row * Dc + lane * 8) = o4;
    } else {
        int i = (blockIdx.x - 1024) * 256 + threadIdx.x;  // float4 idx < 81920
        const float* src;
        __nv_bfloat16* dst;
        int off;
        if (i < 49152)      { src = wq; dst = wqkv_b;  off = i; }
        else if (i < 65536) { src = wo; dst = wout_b;  off = i - 49152; }
        else                { src = wg; dst = wgate_b; off = i - 65536; }
        float4 v = reinterpret_cast<const float4*>(src)[off];
        *reinterpret_cast<uint2*>(dst + off * 4) =
            make_uint2(pack_bf(v.x, v.y), pack_bf(v.z, v.w));
    }
}

// ---------------------------------------------------------------------------
// 1) pipelined bf16 mma GEMM mainloop (cp.async 2-stage, single barrier/iter)
// ---------------------------------------------------------------------------
template <int NOUT>
__device__ __forceinline__ void gemm_main(
    const __nv_bfloat16* __restrict__ A, const __nv_bfloat16* __restrict__ W,
    __nv_bfloat16 (&As)[2][64][LDH], __nv_bfloat16 (&Ws)[2][64][LDH],
    float4 acc[8], int rowBase, int colBase) {
    int tid = threadIdx.x;
    int wid = tid >> 5, lane = tid & 31;
    int wr = wid * 16;
    #pragma unroll
    for (int i = 0; i < 8; i++) acc[i] = make_float4(0.f, 0.f, 0.f, 0.f);

    int lr = tid >> 3, lc8 = (tid & 7) * 8;

    auto load_tile = [&](int s, int k0) {
        #pragma unroll
        for (int j = 0; j < 4; j++) {
            int r = lr + 16 * j;
            cpasync16(&As[s][r][lc8], &A[(rowBase + r) * Dc + k0 + lc8]);
            cpasync16(&Ws[s][r][lc8], &W[(k0 + r) * NOUT + colBase + lc8]);
        }
    };

    load_tile(0, 0);
    cp_commit();

    #pragma unroll
    for (int kc = 0; kc < 4; kc++) {
        cp_wait_all();
        __syncthreads();
        if (kc < 3) {
            load_tile((kc + 1) & 1, (kc + 1) * 64);
            cp_commit();
        }
        int s = kc & 1;
        #pragma unroll
        for (int ks = 0; ks < 4; ks++) {
            unsigned a0, a1, a2, a3;
            ldsm4(a0, a1, a2, a3, &As[s][wr + (lane & 15)][ks * 16 + (lane >> 4) * 8]);
            #pragma unroll
            for (int p = 0; p < 4; p++) {
                unsigned b0, b1, b2, b3;
                ldsm4t(b0, b1, b2, b3,
                       &Ws[s][ks * 16 + (lane & 7) + 8 * ((lane >> 3) & 1)]
                            [p * 16 + (lane >> 4) * 8]);
                mma16(acc[2 * p], a0, a1, a2, a3, b0, b1);
                mma16(acc[2 * p + 1], a0, a1, a2, a3, b2, b3);
            }
        }
    }
}

// QKV GEMM with fused bias + RoPE + head scatter (bf16 outputs; q pre-scaled)
__global__ __launch_bounds__(128) void gemm_qkv_kernel(
    const float* __restrict__ bias, const float* __restrict__ freqs) {
    __shared__ __align__(16) __nv_bfloat16 As[2][64][LDH];
    __shared__ __align__(16) __nv_bfloat16 Ws[2][64][LDH];
    int rowBase = blockIdx.y * 64;
    int colBase = blockIdx.x * 64;
    float4 acc[8];
    gemm_main<3 * Dc>(buf_hb, wqkv_b, As, Ws, acc, rowBase, colBase);

    int tid = threadIdx.x;
    int wid = tid >> 5, lane = tid & 31;
    int gid = lane >> 2, tig = lane & 3;
    int sec = colBase >> 8;  // 0=q 1=k 2=v (uniform per block)
    unsigned* dst = sec == 0 ? reinterpret_cast<unsigned*>(buf_q)
                  : sec == 1 ? reinterpret_cast<unsigned*>(buf_k)
                             : reinterpret_cast<unsigned*>(buf_v);
    float scl = sec == 0 ? QSCALE : 1.f;
    int r0 = rowBase + wid * 16 + gid, r1 = r0 + 8;
    int n0 = r0 & (Nc - 1), n1 = r1 & (Nc - 1);
    int b0i = r0 >> 11, b1i = r1 >> 11;
    #pragma unroll
    for (int nt = 0; nt < 8; nt++) {
        int col = colBase + nt * 8 + tig * 2;
        int c = col & 255, h = c >> 6, i = (c & 63) >> 1;
        float bx = bias[col], by = bias[col + 1];
        float v0 = acc[nt].x + bx, v1 = acc[nt].y + by;
        float w0 = acc[nt].z + bx, w1 = acc[nt].w + by;
        if (sec < 2) {
            float2 cs0 = *reinterpret_cast<const float2*>(&freqs[n0 * 64 + i * 2]);
            float2 cs1 = *reinterpret_cast<const float2*>(&freqs[n1 * 64 + i * 2]);
            float t0 = v0 * cs0.x - v1 * cs0.y;
            v1 = v0 * cs0.y + v1 * cs0.x; v0 = t0;
            float t1 = w0 * cs1.x - w1 * cs1.y;
            w1 = w0 * cs1.y + w1 * cs1.x; w0 = t1;
        }
        v0 *= scl; v1 *= scl; w0 *= scl; w1 *= scl;
        dst[((b0i * Hc + h) * Nc + n0) * 32 + i] = pack_bf(v0, v1);
        dst[((b1i * Hc + h) * Nc + n1) * 32 + i] = pack_bf(w0, w1);
    }
}

// Fused out-proj + gate + residual/gating epilogue
__global__ __launch_bounds__(128) void og_final_kernel(
    const float* __restrict__ bo, const float* __restrict__ bg,
    const float* __restrict__ x, float* __restrict__ out) {
    __shared__ __align__(16) __nv_bfloat16 As[2][64][LDH];
    __shared__ __align__(16) __nv_bfloat16 Ws[2][64][LDH];
    int rowBase = blockIdx.y * 64;
    int colBase = blockIdx.x * 64;
    float4 ao[8], ag[8];
    gemm_main<Dc>(buf_yb, wout_b, As, Ws, ao, rowBase, colBase);
    __syncthreads();   // stage reuse boundary between the two GEMMs
    gemm_main<Dc>(buf_hb, wgate_b, As, Ws, ag, rowBase, colBase);

    int tid = threadIdx.x;
    int wid = tid >> 5, lane = tid & 31;
    int gid = lane >> 2, tig = lane & 3;
    int r0 = rowBase + wid * 16 + gid, r1 = r0 + 8;
    #pragma unroll
    for (int nt = 0; nt < 8; nt++) {
        int col = colBase + nt * 8 + tig * 2;
        float box = bo[col], boy = bo[col + 1];
        float bgx = bg[col], bgy = bg[col + 1];
        float g00 = 1.f / (1.f + __expf(-(ag[nt].x + bgx)));
        float g01 = 1.f / (1.f + __expf(-(ag[nt].y + bgy)));
        float g10 = 1.f / (1.f + __expf(-(ag[nt].z + bgx)));
        float g11 = 1.f / (1.f + __expf(-(ag[nt].w + bgy)));
        float2 x0 = *reinterpret_cast<const float2*>(&x[r0 * Dc + col]);
        float2 x1 = *reinterpret_cast<const float2*>(&x[r1 * Dc + col]);
        *reinterpret_cast<float2*>(&out[r0 * Dc + col]) =
            make_float2(x0.x + g00 * (ao[nt].x + box),
                        x0.y + g01 * (ao[nt].y + boy));
        *reinterpret_cast<float2*>(&out[r1 * Dc + col]) =
            make_float2(x1.x + g10 * (ao[nt].z + box),
                        x1.y + g11 * (ao[nt].w + boy));
    }
}

// ---------------------------------------------------------------------------
// 2) Flash attention. 128 threads, 128 q-rows/block, 4 warps x 2 groups of 16.
//    128-KEY tiles (16 iterations): longer mma bursts, half the barriers.
//    Per n-subtile p: QK mmas then immediate ex2b -> bf16x2 A-frags.
//    Ones-mma row sums. Dynamic smem K/V 2-stage rings.
// ---------------------------------------------------------------------------
__global__ __launch_bounds__(128) void attn_kernel() {
    extern __shared__ __align__(16) __nv_bfloat16 smem[];
    // layout: K[2][128][LDH] then V[2][128][LDH]
    __nv_bfloat16 (*Ks)[128][LDH] =
        reinterpret_cast<__nv_bfloat16 (*)[128][LDH]>(smem);
    __nv_bfloat16 (*Vs)[128][LDH] =
        reinterpret_cast<__nv_bfloat16 (*)[128][LDH]>(smem + 2 * 128 * LDH);

    int tid = threadIdx.x;
    int wid = tid >> 5, lane = tid & 31;
    int gid = lane >> 2, tig = lane & 3;
    int bh = blockIdx.x >> 4;     // 16 bh
    int qt = blockIdx.x & 15;     // 16 q tiles of 128
    int qBase = qt * 128;
    int b = bh >> 2, h = bh & 3;
    const __nv_bfloat16* Q = buf_q + bh * Nc * DHc;
    const __nv_bfloat16* K = buf_k + bh * Nc * DHc;
    const __nv_bfloat16* V = buf_v + bh * Nc * DHc;
    int wr = wid * 16;

    int lr = tid >> 3, lc8 = (tid & 7) * 8;
    auto load_kv = [&](int s, int kb) {
        #pragma unroll
        for (int j = 0; j < 8; j++) {
            int r = lr + 16 * j;
            cpasync16(&Ks[s][r][lc8], &K[(kb + r) * DHc + lc8]);
            cpasync16(&Vs[s][r][lc8], &V[(kb + r) * DHc + lc8]);
        }
    };

    load_kv(0, 0);
    cp_commit();

    // Q A-fragments for both 16-row groups (already scaled by QSCALE)
    unsigned qa[2][4][4];
    #pragma unroll
    for (int g = 0; g < 2; g++) {
        const __nv_bfloat16* qp = Q + (qBase + g * 64 + wr) * DHc;
        #pragma unroll
        for (int ks = 0; ks < 4; ks++) {
            int c = ks * 16 + tig * 2;
            qa[g][ks][0] = *reinterpret_cast<const unsigned*>(&qp[gid * DHc + c]);
            qa[g][ks][1] = *reinterpret_cast<const unsigned*>(&qp[(gid + 8) * DHc + c]);
            qa[g][ks][2] = *reinterpret_cast<const unsigned*>(&qp[gid * DHc + c + 8]);
            qa[g][ks][3] = *reinterpret_cast<const unsigned*>(&qp[(gid + 8) * DHc + c + 8]);
        }
    }

    float4 oacc[2][8];
    float4 lacc[2];   // row sums via ones-mma: .x = row gid, .z = row gid+8
    #pragma unroll
    for (int g = 0; g < 2; g++) {
        lacc[g] = make_float4(0.f, 0.f, 0.f, 0.f);
        #pragma unroll
        for (int i = 0; i < 8; i++) oacc[g][i] = make_float4(0.f, 0.f, 0.f, 0.f);
    }

    #pragma unroll 1
    for (int t = 0; t < 16; t++) {
        cp_wait_all();
        __syncthreads();
        if (t < 15) {
            load_kv((t + 1) & 1, (t + 1) * 128);
            cp_commit();
        }
        int s = t & 1;

        // Per n-subtile p (16 keys): QK mmas for both groups, then ex2b -> pa.
        unsigned pa[2][8][4];
        #pragma unroll
        for (int p = 0; p < 8; p++) {
            float4 s0[2], s1[2];
            #pragma unroll
            for (int g = 0; g < 2; g++) {
                s0[g] = make_float4(0.f, 0.f, 0.f, 0.f);
                s1[g] = make_float4(0.f, 0.f, 0.f, 0.f);
            }
            #pragma unroll
            for (int ks = 0; ks < 4; ks++) {
                unsigned b0, b1, b2, b3;
                ldsm4(b0, b1, b2, b3,
                      &Ks[s][p * 16 + (lane & 7) + 8 * (lane >> 4)]
                           [ks * 16 + 8 * ((lane >> 3) & 1)]);
                #pragma unroll
                for (int g = 0; g < 2; g++) {
                    mma16(s0[g], qa[g][ks][0], qa[g][ks][1],
                          qa[g][ks][2], qa[g][ks][3], b0, b1);
                    mma16(s1[g], qa[g][ks][0], qa[g][ks][1],
                          qa[g][ks][2], qa[g][ks][3], b2, b3);
                }
            }
            #pragma unroll
            for (int g = 0; g < 2; g++) {
                pa[g][p][0] = ex2b(s0[g].x, s0[g].y);
                pa[g][p][1] = ex2b(s0[g].z, s0[g].w);
                pa[g][p][2] = ex2b(s1[g].x, s1[g].y);
                pa[g][p][3] = ex2b(s1[g].z, s1[g].w);
                mma16(lacc[g], pa[g][p][0], pa[g][p][1],
                      pa[g][p][2], pa[g][p][3], ONESBF, ONESBF);
            }
        }

        // O += P V for both groups (k = 128 keys -> 8 k-slabs)
        #pragma unroll
        for (int p = 0; p < 4; p++) {
            #pragma unroll
            for (int ks = 0; ks < 8; ks++) {
                unsigned b0, b1, b2, b3;
                ldsm4t(b0, b1, b2, b3,
                       &Vs[s][ks * 16 + (lane & 7) + 8 * ((lane >> 3) & 1)]
                            [p * 16 + (lane >> 4) * 8]);
                #pragma unroll
                for (int g = 0; g < 2; g++) {
                    mma16(oacc[g][2 * p], pa[g][ks][0], pa[g][ks][1],
                          pa[g][ks][2], pa[g][ks][3], b0, b1);
                    mma16(oacc[g][2 * p + 1], pa[g][ks][0], pa[g][ks][1],
                          pa[g][ks][2], pa[g][ks][3], b2, b3);
                }
            }
        }
    }

    unsigned* Y = reinterpret_cast<unsigned*>(buf_yb);
    #pragma unroll
    for (int g = 0; g < 2; g++) {
        float i0 = 1.f / lacc[g].x, i1 = 1.f / lacc[g].z;
        int r0 = b * Nc + qBase + g * 64 + wr + gid, r1 = r0 + 8;
        #pragma unroll
        for (int nt = 0; nt < 8; nt++) {
            int cw = 32 * h + 4 * nt + tig;   // bf162 word index within row
            Y[r0 * 128 + cw] = pack_bf(oacc[g][nt].x * i0, oacc[g][nt].y * i0);
            Y[r1 * 128 + cw] = pack_bf(oacc[g][nt].z * i1, oacc[g][nt].w * i1);
        }
    }
}

// ---------------------------------------------------------------------------
extern "C" void kernel_launch(void* const* d_in, const int* in_sizes, int n_in,
                              void* d_out, int out_size) {
    (void)in_sizes; (void)n_in; (void)out_size;
    const float* x      = (const float*)d_in[0];
    const float* freqs  = (const float*)d_in[1];
    const float* g      = (const float*)d_in[2];
    const float* w_qkv  = (const float*)d_in[3];
    const float* b_qkv  = (const float*)d_in[4];
    const float* w_out  = (const float*)d_in[5];
    const float* b_out  = (const float*)d_in[6];
    const float* w_gate = (const float*)d_in[7];
    const float* b_gate = (const float*)d_in[8];
    float* out = (float*)d_out;

    static bool attr_set = false;
    if (!attr_set) {
        cudaFuncSetAttribute(attn_kernel,
                             cudaFuncAttributeMaxDynamicSharedMemorySize, ATTN_SMEM);
        attr_set = true;
    }

    pre_kernel<<<1344, 256>>>(x, g, w_qkv, w_out, w_gate);
    gemm_qkv_kernel<<<dim3(12, 128), 128>>>(b_qkv, freqs);
    attn_kernel<<<Bc * Hc * (Nc / 128), 128, ATTN_SMEM>>>();
    og_final_kernel<<<dim3(4, 128), 128>>>(b_out, b_gate, x, out);
}